// round 12
// baseline (speedup 1.0000x reference)
#include <cuda_runtime.h>
#include <cuda_bf16.h>
#include <math.h>
#include <stdint.h>

#define Vv    32000
#define Cc    768
#define Tt    1024
#define Hh    12
#define FFf   9216
#define NB    3
#define Mrows 4096
#define QKVN  2304
#define NBATCH 4
#define LOGITS_N 131072000LL
#define ATT_SCALE 0.036084391824351615f

typedef __nv_bfloat16 bf16;

// ---- scratch (device globals; no runtime allocation) ----
__device__ float g_x   [Mrows*Cc];
__device__ float g_qkv [Mrows*QKVN];
__device__ __align__(128) bf16 g_asp [(size_t)Mrows*2304];        // split activations [M, 3*768] = [hi|lo|hi]
__device__ __align__(128) bf16 g_ffsp[(size_t)Mrows*27648];       // split FF activations [M, 3*9216]
__device__ float g_rowloss[Mrows];
// split, transposed weights: [N, 3K] bf16, K-major, [hi | hi | lo]
__device__ __align__(128) bf16 g_wqkvB [(size_t)NB*2304*2304];
__device__ __align__(128) bf16 g_wprojB[(size_t)NB*768*2304];
__device__ __align__(128) bf16 g_wf1B  [(size_t)NB*9216*2304];
__device__ __align__(128) bf16 g_wf2B  [(size_t)NB*768*27648];
__device__ __align__(128) bf16 g_wlmB  [(size_t)Vv*2304];

// ================= PTX helpers (arch-portable, sm_80+) =================
__device__ __forceinline__ uint32_t smem_u32(const void* p) {
    uint32_t a;
    asm("{ .reg .u64 t; cvta.to.shared.u64 t, %1; cvt.u32.u64 %0, t; }" : "=r"(a) : "l"(p));
    return a;
}
#define CP16(dst, src)  asm volatile("cp.async.cg.shared.global [%0], [%1], 16;" :: "r"(dst), "l"(src))
#define CP_COMMIT()     asm volatile("cp.async.commit_group;" ::: "memory")
#define CP_WAITG(n)     asm volatile("cp.async.wait_group %0;" :: "n"(n) : "memory")

__device__ __forceinline__ void ldm_x4(uint32_t* r, uint32_t addr) {
    asm volatile("ldmatrix.sync.aligned.m8n8.x4.shared.b16 {%0,%1,%2,%3}, [%4];"
        : "=r"(r[0]), "=r"(r[1]), "=r"(r[2]), "=r"(r[3]) : "r"(addr));
}
__device__ __forceinline__ void mma16816(float* c, const uint32_t* a, const uint32_t* b) {
    asm volatile("mma.sync.aligned.m16n8k16.row.col.f32.bf16.bf16.f32 "
        "{%0,%1,%2,%3}, {%4,%5,%6,%7}, {%8,%9}, {%0,%1,%2,%3};"
        : "+f"(c[0]), "+f"(c[1]), "+f"(c[2]), "+f"(c[3])
        : "r"(a[0]), "r"(a[1]), "r"(a[2]), "r"(a[3]), "r"(b[0]), "r"(b[1]));
}

__device__ __forceinline__ void split_store(bf16* p, size_t o, size_t K, float v) {
    bf16 h = __float2bfloat16(v);
    bf16 l = __float2bfloat16(v - __bfloat162float(h));
    p[o] = h; p[o + K] = l; p[o + 2*K] = h;   // A layout: [hi | lo | hi]
}

#define SSTR 40   // smem row stride in bf16 (80B): conflict-free ldmatrix
#define NSTG 3

// ================= HMMA GEMM, 128x128 tile (for small-N GEMMs) =================
// MODE 0: outF = acc (+bias)   MODE 1: relu(acc+bias) -> split bf16 outS
// MODE 2: outF = acc + bias + res
template<int MODE>
__global__ void __launch_bounds__(256, 2)
hmma_gemm(const bf16* __restrict__ A, const bf16* __restrict__ Bw,
          const float* __restrict__ bias, const float* __restrict__ res,
          float* __restrict__ outF, bf16* __restrict__ outS,
          int K3, int N, int KoutS)
{
    __shared__ __align__(16) bf16 As[NSTG][128 * SSTR];
    __shared__ __align__(16) bf16 Bs[NSTG][128 * SSTR];

    int tid = threadIdx.x, lane = tid & 31, wid = tid >> 5;
    int warp_m = wid & 3, warp_n = wid >> 2;       // 4 x 2 warps, warp tile 32x64
    int gm = blockIdx.x, gn = blockIdx.y;

    const bf16* Aptr = A  + (size_t)(gm * 128) * K3;
    const bf16* Bptr = Bw + (size_t)(gn * 128) * K3;

    float acc[2][8][4];
#pragma unroll
    for (int i = 0; i < 2; i++)
#pragma unroll
        for (int j = 0; j < 8; j++)
#pragma unroll
            for (int q = 0; q < 4; q++) acc[i][j][q] = 0.f;

    int r0 = tid >> 2, sub = (tid & 3) * 8;

    auto load_tiles = [&](int stage, int k0) {
        uint32_t sa = smem_u32(&As[stage][0]);
        uint32_t sb = smem_u32(&Bs[stage][0]);
#pragma unroll
        for (int hf = 0; hf < 2; hf++) {
            int row = r0 + hf * 64;
            CP16(sa + (row * SSTR + sub) * 2, Aptr + (size_t)row * K3 + k0 + sub);
            CP16(sb + (row * SSTR + sub) * 2, Bptr + (size_t)row * K3 + k0 + sub);
        }
        CP_COMMIT();
    };

    int NK = K3 / 32;
    load_tiles(0, 0);
    load_tiles(1, 32);

    for (int it = 0; it < NK; it++) {
        CP_WAITG(1);
        __syncthreads();

        int nx = it + NSTG - 1;
        if (nx < NK) load_tiles(nx % NSTG, nx * 32);

        int st = it % NSTG;
        uint32_t abase = smem_u32(&As[st][0]);
        uint32_t bbase = smem_u32(&Bs[st][0]);
#pragma unroll
        for (int kk = 0; kk < 32; kk += 16) {
            uint32_t af[2][4], bfr[4][4];
#pragma unroll
            for (int mt = 0; mt < 2; mt++) {
                int row = warp_m * 32 + mt * 16 + (lane & 15);
                int col = kk + (lane >> 4) * 8;
                ldm_x4(af[mt], abase + (row * SSTR + col) * 2);
            }
#pragma unroll
            for (int bt = 0; bt < 4; bt++) {
                int row = warp_n * 64 + bt * 16 + (lane & 15);
                int col = kk + (lane >> 4) * 8;
                ldm_x4(bfr[bt], bbase + (row * SSTR + col) * 2);
            }
#pragma unroll
            for (int mt = 0; mt < 2; mt++)
#pragma unroll
                for (int bt = 0; bt < 4; bt++) {
                    uint32_t blo[2] = { bfr[bt][0], bfr[bt][2] };
                    uint32_t bhi[2] = { bfr[bt][1], bfr[bt][3] };
                    mma16816(acc[mt][bt * 2 + 0], af[mt], blo);
                    mma16816(acc[mt][bt * 2 + 1], af[mt], bhi);
                }
        }
    }

    int rbase = gm * 128 + warp_m * 32;
    int cbase = gn * 128 + warp_n * 64;
#pragma unroll
    for (int mt = 0; mt < 2; mt++) {
#pragma unroll
        for (int nt = 0; nt < 8; nt++) {
#pragma unroll
            for (int hf = 0; hf < 2; hf++) {
                int grow = rbase + mt * 16 + (lane >> 2) + hf * 8;
                int gcol = cbase + nt * 8 + (lane & 3) * 2;
                float v0 = acc[mt][nt][hf * 2 + 0];
                float v1 = acc[mt][nt][hf * 2 + 1];
                if (bias) { v0 += bias[gcol]; v1 += bias[gcol + 1]; }
                if (MODE == 2) {
                    const float* rr = res + (size_t)grow * N + gcol;
                    v0 += rr[0]; v1 += rr[1];
                }
                if (MODE == 1) {
                    v0 = fmaxf(v0, 0.f); v1 = fmaxf(v1, 0.f);
                    size_t o = (size_t)grow * (3 * (size_t)KoutS) + gcol;
                    split_store(outS, o,     KoutS, v0);
                    split_store(outS, o + 1, KoutS, v1);
                } else {
                    float* po = outF + (size_t)grow * N + gcol;
                    po[0] = v0; po[1] = v1;
                }
            }
        }
    }
}

// ================= HMMA GEMM, 256x128 tile (QKV / FF1 / LM head) =================
// 8 warps (4m x 2n), warp tile 64x64, 128 accum regs/thread, 1 CTA/SM.
template<int MODE>
__global__ void __launch_bounds__(256)
hmma_gemm256(const bf16* __restrict__ A, const bf16* __restrict__ Bw,
             const float* __restrict__ bias,
             float* __restrict__ outF, bf16* __restrict__ outS,
             int K3, int N, int KoutS)
{
    __shared__ __align__(16) bf16 As[NSTG][256 * SSTR];
    __shared__ __align__(16) bf16 Bs[NSTG][128 * SSTR];

    int tid = threadIdx.x, lane = tid & 31, wid = tid >> 5;
    int warp_m = wid & 3, warp_n = wid >> 2;       // warp tile 64x64
    int gm = blockIdx.x, gn = blockIdx.y;

    const bf16* Aptr = A  + (size_t)(gm * 256) * K3;
    const bf16* Bptr = Bw + (size_t)(gn * 128) * K3;

    float acc[4][8][4];
#pragma unroll
    for (int i = 0; i < 4; i++)
#pragma unroll
        for (int j = 0; j < 8; j++)
#pragma unroll
            for (int q = 0; q < 4; q++) acc[i][j][q] = 0.f;

    auto load_tiles = [&](int stage, int k0) {
        uint32_t sa = smem_u32(&As[stage][0]);
        uint32_t sb = smem_u32(&Bs[stage][0]);
#pragma unroll
        for (int it2 = 0; it2 < 4; it2++) {         // A: 256 rows, 1024 segs
            int e = tid + it2 * 256;
            int row = e >> 2, sub = (e & 3) * 8;
            CP16(sa + (row * SSTR + sub) * 2, Aptr + (size_t)row * K3 + k0 + sub);
        }
#pragma unroll
        for (int it2 = 0; it2 < 2; it2++) {         // B: 128 rows, 512 segs
            int e = tid + it2 * 256;
            int row = e >> 2, sub = (e & 3) * 8;
            CP16(sb + (row * SSTR + sub) * 2, Bptr + (size_t)row * K3 + k0 + sub);
        }
        CP_COMMIT();
    };

    int NK = K3 / 32;
    load_tiles(0, 0);
    load_tiles(1, 32);

    for (int it = 0; it < NK; it++) {
        CP_WAITG(1);
        __syncthreads();

        int nx = it + NSTG - 1;
        if (nx < NK) load_tiles(nx % NSTG, nx * 32);

        int st = it % NSTG;
        uint32_t abase = smem_u32(&As[st][0]);
        uint32_t bbase = smem_u32(&Bs[st][0]);
#pragma unroll
        for (int kk = 0; kk < 32; kk += 16) {
            uint32_t af[4][4], bfr[4][4];
#pragma unroll
            for (int mt = 0; mt < 4; mt++) {
                int row = warp_m * 64 + mt * 16 + (lane & 15);
                int col = kk + (lane >> 4) * 8;
                ldm_x4(af[mt], abase + (row * SSTR + col) * 2);
            }
#pragma unroll
            for (int bt = 0; bt < 4; bt++) {
                int row = warp_n * 64 + bt * 16 + (lane & 15);
                int col = kk + (lane >> 4) * 8;
                ldm_x4(bfr[bt], bbase + (row * SSTR + col) * 2);
            }
#pragma unroll
            for (int mt = 0; mt < 4; mt++)
#pragma unroll
                for (int bt = 0; bt < 4; bt++) {
                    uint32_t blo[2] = { bfr[bt][0], bfr[bt][2] };
                    uint32_t bhi[2] = { bfr[bt][1], bfr[bt][3] };
                    mma16816(acc[mt][bt * 2 + 0], af[mt], blo);
                    mma16816(acc[mt][bt * 2 + 1], af[mt], bhi);
                }
        }
    }

    int rbase = gm * 256 + warp_m * 64;
    int cbase = gn * 128 + warp_n * 64;
#pragma unroll
    for (int mt = 0; mt < 4; mt++) {
#pragma unroll
        for (int nt = 0; nt < 8; nt++) {
#pragma unroll
            for (int hf = 0; hf < 2; hf++) {
                int grow = rbase + mt * 16 + (lane >> 2) + hf * 8;
                int gcol = cbase + nt * 8 + (lane & 3) * 2;
                float v0 = acc[mt][nt][hf * 2 + 0];
                float v1 = acc[mt][nt][hf * 2 + 1];
                if (bias) { v0 += bias[gcol]; v1 += bias[gcol + 1]; }
                if (MODE == 1) {
                    v0 = fmaxf(v0, 0.f); v1 = fmaxf(v1, 0.f);
                    size_t o = (size_t)grow * (3 * (size_t)KoutS) + gcol;
                    split_store(outS, o,     KoutS, v0);
                    split_store(outS, o + 1, KoutS, v1);
                } else {
                    float* po = outF + (size_t)grow * N + gcol;
                    po[0] = v0; po[1] = v1;
                }
            }
        }
    }
}

// ================= weight packing =================
__device__ __forceinline__ void tsplit_body(const float* __restrict__ src,
                                            bf16* __restrict__ dst,
                                            int K, int N, int n0, int k0,
                                            int tx, int ty, float (*t)[33]) {
#pragma unroll
    for (int i = 0; i < 32; i += 8) t[ty + i][tx] = src[(size_t)(k0 + ty + i) * N + n0 + tx];
    __syncthreads();
#pragma unroll
    for (int i = 0; i < 32; i += 8) {
        float v = t[tx][ty + i];
        int n = n0 + ty + i, k = k0 + tx;
        bf16 h = __float2bfloat16(v);
        bf16 l = __float2bfloat16(v - __bfloat162float(h));
        size_t o = (size_t)n * (3 * (size_t)K) + k;
        dst[o] = h; dst[o + K] = h; dst[o + 2 * K] = l;
    }
}

// src [K,N] fp32 -> dst [N,3K] bf16 K-major: [hi | hi | lo]
__global__ void tsplit_kernel(const float* __restrict__ src, bf16* __restrict__ dst,
                              int K, int N) {
    __shared__ float t[32][33];
    tsplit_body(src, dst, K, N, blockIdx.x * 32, blockIdx.y * 32,
                threadIdx.x, threadIdx.y, t);
}

// all proj/f1/f2 packs in ONE launch (14400 tiles per block x 3 blocks)
__global__ void tsplit_multi(const float* __restrict__ wproj,
                             const float* __restrict__ wf1,
                             const float* __restrict__ wf2) {
    __shared__ float t[32][33];
    int id = blockIdx.x;
    int blk = id / 14400, r = id % 14400;
    const float* src; bf16* dst; int K, N, tn, tk;
    if (r < 576) {
        src = wproj + (size_t)blk * 768 * 768;  dst = g_wprojB + (size_t)blk * 768 * 2304;
        K = 768; N = 768; tn = r % 24; tk = r / 24;
    } else if (r < 7488) {
        int q = r - 576;
        src = wf1 + (size_t)blk * 768 * 9216;   dst = g_wf1B + (size_t)blk * 9216 * 2304;
        K = 768; N = 9216; tn = q % 288; tk = q / 288;
    } else {
        int q = r - 7488;
        src = wf2 + (size_t)blk * 9216 * 768;   dst = g_wf2B + (size_t)blk * 768 * 27648;
        K = 9216; N = 768; tn = q % 24; tk = q / 24;
    }
    tsplit_body(src, dst, K, N, tn * 32, tk * 32, threadIdx.x, threadIdx.y, t);
}

// wq/wk/wv [blk][H][768][64] -> g_wqkvB [blk][N=2304][3K=2304]
__global__ void qkvpack_kernel(const float* __restrict__ wq, const float* __restrict__ wk,
                               const float* __restrict__ wv) {
    __shared__ float t[32][33];
    int z = blockIdx.z;
    int blk = z / 36, rem = z % 36, mat = rem / 12, h = rem % 12;
    const float* src = (mat == 0 ? wq : mat == 1 ? wk : wv) + (size_t)(blk * 12 + h) * 768 * 64;
    int d0 = blockIdx.x * 32, c0 = blockIdx.y * 32;
    int tx = threadIdx.x, ty = threadIdx.y;
#pragma unroll
    for (int i = 0; i < 32; i += 8) t[ty + i][tx] = src[(size_t)(c0 + ty + i) * 64 + d0 + tx];
    __syncthreads();
    bf16* dst = g_wqkvB + (size_t)blk * 2304 * 2304;
#pragma unroll
    for (int i = 0; i < 32; i += 8) {
        float v = t[tx][ty + i];
        int n = mat * 768 + h * 64 + d0 + ty + i;
        int c = c0 + tx;
        bf16 hh = __float2bfloat16(v);
        bf16 ll = __float2bfloat16(v - __bfloat162float(hh));
        size_t o = (size_t)n * 2304 + c;
        dst[o] = hh; dst[o + 768] = hh; dst[o + 1536] = ll;
    }
}

// ================= embed =================
__global__ void embed_kernel(const float* __restrict__ tok, const float* __restrict__ pos,
                             const int* __restrict__ src) {
    int idx = blockIdx.x * blockDim.x + threadIdx.x;
    if (idx >= Mrows * Cc) return;
    int r = idx / Cc, c = idx % Cc;
    g_x[idx] = tok[(size_t)src[r] * Cc + c] + pos[(size_t)(r % Tt) * Cc + c];
}

// ================= LayerNorm -> split bf16 =================
__global__ void ln_kernel(const float* __restrict__ x, const float* __restrict__ g,
                          const float* __restrict__ b) {
    int r = blockIdx.x, tid = threadIdx.x;
    const float* xr = x + (size_t)r * Cc;
    float vals[3];
    float s = 0.f, ss = 0.f;
#pragma unroll
    for (int i = 0; i < 3; i++) {
        float v = xr[tid + i * 256];
        vals[i] = v; s += v; ss += v * v;
    }
#pragma unroll
    for (int o = 16; o; o >>= 1) {
        s  += __shfl_xor_sync(0xffffffffu, s,  o);
        ss += __shfl_xor_sync(0xffffffffu, ss, o);
    }
    __shared__ float sh_s[8], sh_ss[8], smean, srstd;
    int w = tid >> 5, l = tid & 31;
    if (l == 0) { sh_s[w] = s; sh_ss[w] = ss; }
    __syncthreads();
    if (tid == 0) {
        float S = 0.f, SS = 0.f;
        for (int i = 0; i < 8; i++) { S += sh_s[i]; SS += sh_ss[i]; }
        float m = S / Cc;
        smean = m; srstd = rsqrtf(SS / Cc - m * m + 1e-5f);
    }
    __syncthreads();
    float m = smean, rstd = srstd;
#pragma unroll
    for (int i = 0; i < 3; i++) {
        int c = tid + i * 256;
        float y = (vals[i] - m) * rstd * g[c] + b[c];
        split_store(g_asp, (size_t)r * 2304 + c, 768, y);
    }
}

// ================= causal attention (fp32), split output =================
__global__ void __launch_bounds__(256)
attn_kernel(const float* __restrict__ QKV) {
    int bh = blockIdx.x;
    int b = bh / Hh, h = bh % Hh;
    int qt0 = blockIdx.y * 64;
    int tid = threadIdx.x;

    __shared__ float Qs[64][64];
    __shared__ float Ks[32][65];
    __shared__ float Vs[32][65];
    __shared__ float Ps[64][33];
    __shared__ float mrow[64], lrow[64], arow_s[64];

#pragma unroll
    for (int i = 0; i < 16; i++) {
        int e = tid + i * 256;
        int r = e >> 6, d = e & 63;
        Qs[r][d] = QKV[((size_t)(b * Tt + qt0 + r)) * QKVN + h * 64 + d];
    }
    if (tid < 64) { mrow[tid] = -1e30f; lrow[tid] = 0.f; }

    float o[16];
#pragma unroll
    for (int i = 0; i < 16; i++) o[i] = 0.f;

    int d_o = tid & 63, rg_o = tid >> 6;
    int s_s = tid & 31, rg_s = tid >> 5;

    int nkt = (qt0 + 64) / 32;
    for (int kt = 0; kt < nkt; kt++) {
        __syncthreads();
#pragma unroll
        for (int i = 0; i < 8; i++) {
            int e = tid + i * 256;
            int s = e >> 6, d = e & 63;
            size_t gi = ((size_t)(b * Tt + kt * 32 + s)) * QKVN + h * 64 + d;
            Ks[s][d] = QKV[gi + 768];
            Vs[s][d] = QKV[gi + 1536];
        }
        __syncthreads();
#pragma unroll
        for (int i = 0; i < 8; i++) {
            int r = rg_s * 8 + i;
            float a = 0.f;
#pragma unroll
            for (int k = 0; k < 64; k++) a += Qs[r][k] * Ks[s_s][k];
            int sg = kt * 32 + s_s, tg = qt0 + r;
            Ps[r][s_s] = (sg <= tg) ? a * ATT_SCALE : -1e30f;
        }
        __syncthreads();
        if (tid < 64) {
            int r = tid;
            float m_old = mrow[r], mx = m_old;
#pragma unroll
            for (int s = 0; s < 32; s++) mx = fmaxf(mx, Ps[r][s]);
            float alpha = expf(m_old - mx), sum = 0.f;
#pragma unroll
            for (int s = 0; s < 32; s++) { float p = expf(Ps[r][s] - mx); Ps[r][s] = p; sum += p; }
            mrow[r] = mx; lrow[r] = lrow[r] * alpha + sum; arow_s[r] = alpha;
        }
        __syncthreads();
#pragma unroll
        for (int i = 0; i < 16; i++) {
            int r = rg_o * 16 + i;
            float al = arow_s[r], a = 0.f;
#pragma unroll
            for (int s = 0; s < 32; s++) a += Ps[r][s] * Vs[s][d_o];
            o[i] = o[i] * al + a;
        }
    }
#pragma unroll
    for (int i = 0; i < 16; i++) {
        int r = rg_o * 16 + i;
        float v = o[i] / lrow[r];
        split_store(g_asp, ((size_t)(b * Tt + qt0 + r)) * 2304 + h * 64 + d_o, 768, v);
    }
}

// ================= loss (one-pass online softmax) =================
__global__ void loss_rows_kernel(const float* __restrict__ logits, const int* __restrict__ targets) {
    int r = blockIdx.x, tid = threadIdx.x;
    const float* row = logits + (size_t)r * Vv;
    float mx = -1e30f, s = 0.f;
    for (int c = tid; c < Vv; c += 256) {
        float v = row[c];
        if (v > mx) { s = s * expf(mx - v) + 1.f; mx = v; }
        else        { s += expf(v - mx); }
    }
#pragma unroll
    for (int o = 16; o; o >>= 1) {
        float mo = __shfl_xor_sync(0xffffffffu, mx, o);
        float so = __shfl_xor_sync(0xffffffffu, s,  o);
        float M = fmaxf(mx, mo);
        s = s * expf(mx - M) + so * expf(mo - M);
        mx = M;
    }
    __shared__ float shm[8], shs[8];
    int w = tid >> 5;
    if ((tid & 31) == 0) { shm[w] = mx; shs[w] = s; }
    __syncthreads();
    if (tid == 0) {
        float M = shm[0];
        for (int i = 1; i < 8; i++) M = fmaxf(M, shm[i]);
        float S = 0.f;
        for (int i = 0; i < 8; i++) S += shs[i] * expf(shm[i] - M);
        g_rowloss[r] = M + logf(S) - row[targets[r]];
    }
}

__global__ void loss_reduce_kernel(float* __restrict__ d_out, long long out_size) {
    int tid = threadIdx.x;
    __shared__ float sh[8];
    float s = 0.f;
    for (int i = tid; i < Mrows; i += 256) s += g_rowloss[i];
#pragma unroll
    for (int o = 16; o; o >>= 1) s += __shfl_xor_sync(0xffffffffu, s, o);
    if ((tid & 31) == 0) sh[tid >> 5] = s;
    __syncthreads();
    if (tid == 0) {
        float S = 0.f;
        for (int i = 0; i < 8; i++) S += sh[i];
        float loss = S / (float)Mrows;
        for (long long i = LOGITS_N; i < out_size; i++) d_out[i] = loss;
    }
}

// ================= host orchestration =================
extern "C" void kernel_launch(void* const* d_in, const int* in_sizes, int n_in,
                              void* d_out, int out_size) {
    const float* tok_emb = (const float*)d_in[0];
    const float* pos_emb = (const float*)d_in[1];
    const float* wq      = (const float*)d_in[2];
    const float* wk      = (const float*)d_in[3];
    const float* wv      = (const float*)d_in[4];
    const float* wproj   = (const float*)d_in[5];
    const float* bproj   = (const float*)d_in[6];
    const float* g1      = (const float*)d_in[7];
    const float* b1      = (const float*)d_in[8];
    const float* g2      = (const float*)d_in[9];
    const float* b2      = (const float*)d_in[10];
    const float* wf1     = (const float*)d_in[11];
    const float* bf1     = (const float*)d_in[12];
    const float* wf2     = (const float*)d_in[13];
    const float* bf2     = (const float*)d_in[14];
    const float* gf      = (const float*)d_in[15];
    const float* bfv     = (const float*)d_in[16];
    const float* wlm     = (const float*)d_in[17];
    const float* blm     = (const float*)d_in[18];
    const int*   sources = (const int*)d_in[19];
    const int*   targets = (const int*)d_in[20];
    float* out = (float*)d_out;

    float *px, *pqkv;
    bf16 *pasp, *pffsp, *pwqkv, *pwproj, *pwf1, *pwf2, *pwlm;
    cudaGetSymbolAddress((void**)&px,    g_x);
    cudaGetSymbolAddress((void**)&pqkv,  g_qkv);
    cudaGetSymbolAddress((void**)&pasp,  g_asp);
    cudaGetSymbolAddress((void**)&pffsp, g_ffsp);
    cudaGetSymbolAddress((void**)&pwqkv, g_wqkvB);
    cudaGetSymbolAddress((void**)&pwproj,g_wprojB);
    cudaGetSymbolAddress((void**)&pwf1,  g_wf1B);
    cudaGetSymbolAddress((void**)&pwf2,  g_wf2B);
    cudaGetSymbolAddress((void**)&pwlm,  g_wlmB);

    // launch order arranged so ncu (-s 5 -c 1) captures the first hmma_gemm256
    embed_kernel<<<(Mrows * Cc + 255) / 256, 256>>>(tok_emb, pos_emb, sources);     // 1
    ln_kernel<<<Mrows, 256>>>(px, g1 + 0 * Cc, b1 + 0 * Cc);                        // 2
    dim3 tb32(32, 8);
    qkvpack_kernel<<<dim3(2, 24, 108), tb32>>>(wq, wk, wv);                         // 3
    tsplit_multi<<<43200, tb32>>>(wproj, wf1, wf2);                                 // 4
    tsplit_kernel<<<dim3(1000, 24), tb32>>>(wlm, pwlm, 768, Vv);                    // 5

    for (int i = 0; i < NB; i++) {
        if (i > 0) ln_kernel<<<Mrows, 256>>>(px, g1 + i * Cc, b1 + i * Cc);
        hmma_gemm256<0><<<dim3(16, 18), 256>>>(                                     // 6 on i=0
            pasp, pwqkv + (size_t)i*2304*2304, nullptr, pqkv, nullptr, 2304, QKVN, 0);
        attn_kernel<<<dim3(NBATCH * Hh, Tt / 64), 256>>>(pqkv);
        hmma_gemm<2><<<dim3(32, 6), 256>>>(
            pasp, pwproj + (size_t)i*768*2304, bproj + i * Cc, px, px, nullptr, 2304, Cc, 0);
        ln_kernel<<<Mrows, 256>>>(px, g2 + i * Cc, b2 + i * Cc);
        hmma_gemm256<1><<<dim3(16, 72), 256>>>(
            pasp, pwf1 + (size_t)i*9216*2304, bf1 + i * FFf, nullptr, pffsp, 2304, FFf, FFf);
        hmma_gemm<2><<<dim3(32, 6), 256>>>(
            pffsp, pwf2 + (size_t)i*768*27648, bf2 + i * Cc, px, px, nullptr, 27648, Cc, 0);
    }

    ln_kernel<<<Mrows, 256>>>(px, gf, bfv);
    hmma_gemm256<0><<<dim3(16, 250), 256>>>(
        pasp, pwlm, blm, out, nullptr, 2304, Vv, 0);

    loss_rows_kernel<<<Mrows, 256>>>(out, targets);
    loss_reduce_kernel<<<1, 256>>>(out, (long long)out_size);
}

// round 14
// speedup vs baseline: 1.1568x; 1.1568x over previous
#include <cuda_runtime.h>
#include <cuda_bf16.h>
#include <math.h>
#include <stdint.h>

#define Vv    32000
#define Cc    768
#define Tt    1024
#define Hh    12
#define FFf   9216
#define NB    3
#define Mrows 4096
#define QKVN  2304
#define NBATCH 4
#define LOGITS_N 131072000LL
#define ATT_SCALE 0.036084391824351615f

typedef __nv_bfloat16 bf16;

// ---- scratch (device globals; no runtime allocation) ----
__device__ float g_x   [Mrows*Cc];
__device__ float g_qkv [Mrows*QKVN];
__device__ __align__(128) bf16 g_asp [(size_t)Mrows*2304];        // split activations [M, 3*768] = [hi|lo|hi]
__device__ __align__(128) bf16 g_ffsp[(size_t)Mrows*27648];       // split FF activations [M, 3*9216]
__device__ float g_rowloss[Mrows];
// split, transposed weights: [N, 3K] bf16, K-major, [hi | hi | lo]
__device__ __align__(128) bf16 g_wqkvB [(size_t)NB*2304*2304];
__device__ __align__(128) bf16 g_wprojB[(size_t)NB*768*2304];
__device__ __align__(128) bf16 g_wf1B  [(size_t)NB*9216*2304];
__device__ __align__(128) bf16 g_wf2B  [(size_t)NB*768*27648];
__device__ __align__(128) bf16 g_wlmB  [(size_t)Vv*2304];

// ================= PTX helpers (arch-portable, sm_80+) =================
__device__ __forceinline__ uint32_t smem_u32(const void* p) {
    uint32_t a;
    asm("{ .reg .u64 t; cvta.to.shared.u64 t, %1; cvt.u32.u64 %0, t; }" : "=r"(a) : "l"(p));
    return a;
}
#define CP16(dst, src)  asm volatile("cp.async.cg.shared.global [%0], [%1], 16;" :: "r"(dst), "l"(src))
#define CP_COMMIT()     asm volatile("cp.async.commit_group;" ::: "memory")
#define CP_WAITG(n)     asm volatile("cp.async.wait_group %0;" :: "n"(n) : "memory")

__device__ __forceinline__ void ldm_x4(uint32_t* r, uint32_t addr) {
    asm volatile("ldmatrix.sync.aligned.m8n8.x4.shared.b16 {%0,%1,%2,%3}, [%4];"
        : "=r"(r[0]), "=r"(r[1]), "=r"(r[2]), "=r"(r[3]) : "r"(addr));
}
__device__ __forceinline__ void mma16816(float* c, const uint32_t* a, const uint32_t* b) {
    asm volatile("mma.sync.aligned.m16n8k16.row.col.f32.bf16.bf16.f32 "
        "{%0,%1,%2,%3}, {%4,%5,%6,%7}, {%8,%9}, {%0,%1,%2,%3};"
        : "+f"(c[0]), "+f"(c[1]), "+f"(c[2]), "+f"(c[3])
        : "r"(a[0]), "r"(a[1]), "r"(a[2]), "r"(a[3]), "r"(b[0]), "r"(b[1]));
}

__device__ __forceinline__ void split_store(bf16* p, size_t o, size_t K, float v) {
    bf16 h = __float2bfloat16(v);
    bf16 l = __float2bfloat16(v - __bfloat162float(h));
    p[o] = h; p[o + K] = l; p[o + 2*K] = h;   // A layout: [hi | lo | hi]
}

// ================= HMMA GEMM =================
// C[M,N] = A'[M,K3] @ B'[N,K3]^T  (bf16, fp32 accum)
// Tile 128x128, BK=64 per pipeline round, double-buffered,
// 256 threads, 8 warps (4m x 2n, warp tile 32x64), 2 CTAs/SM.
// Smem rows hold 64 K-cols, stride 72 bf16 (144B): ldmatrix rows start at
// banks {0,4,8,...,28} (disjoint 16B spans) -> conflict-free.
// MODE 0: outF = acc (+bias)   MODE 1: relu(acc+bias) -> split bf16 outS
// MODE 2: outF = acc + bias + res
#define SSTR 72
template<int MODE>
__global__ void __launch_bounds__(256, 2)
hmma_gemm(const bf16* __restrict__ A, const bf16* __restrict__ Bw,
          const float* __restrict__ bias, const float* __restrict__ res,
          float* __restrict__ outF, bf16* __restrict__ outS,
          int K3, int N, int KoutS)
{
    __shared__ __align__(16) bf16 As[2][128 * SSTR];
    __shared__ __align__(16) bf16 Bs[2][128 * SSTR];

    int tid = threadIdx.x, lane = tid & 31, wid = tid >> 5;
    int warp_m = wid & 3, warp_n = wid >> 2;       // 4 x 2 warps, warp tile 32x64
    int gm = blockIdx.x, gn = blockIdx.y;

    const bf16* Aptr = A  + (size_t)(gm * 128) * K3;
    const bf16* Bptr = Bw + (size_t)(gn * 128) * K3;

    float acc[2][8][4];
#pragma unroll
    for (int i = 0; i < 2; i++)
#pragma unroll
        for (int j = 0; j < 8; j++)
#pragma unroll
            for (int q = 0; q < 4; q++) acc[i][j][q] = 0.f;

    // stage = 128 rows x 64 bf16 = 8192 elems = 1024 16B-segs per operand
    auto load_tiles = [&](int stage, int k0) {
        uint32_t sa = smem_u32(&As[stage][0]);
        uint32_t sb = smem_u32(&Bs[stage][0]);
#pragma unroll
        for (int it2 = 0; it2 < 4; it2++) {
            int e = tid + it2 * 256;
            int row = e >> 3, sub = (e & 7) * 8;
            CP16(sa + (row * SSTR + sub) * 2, Aptr + (size_t)row * K3 + k0 + sub);
        }
#pragma unroll
        for (int it2 = 0; it2 < 4; it2++) {
            int e = tid + it2 * 256;
            int row = e >> 3, sub = (e & 7) * 8;
            CP16(sb + (row * SSTR + sub) * 2, Bptr + (size_t)row * K3 + k0 + sub);
        }
        CP_COMMIT();
    };

    int NK = K3 / 64;
    load_tiles(0, 0);

    for (int it = 0; it < NK; it++) {
        CP_WAITG(0);           // chunk it resident (only pending group)
        __syncthreads();       // prev compute done before overwrite; loads visible

        if (it + 1 < NK) load_tiles((it + 1) & 1, (it + 1) * 64);  // overlaps compute

        int st = it & 1;
        uint32_t abase = smem_u32(&As[st][0]);
        uint32_t bbase = smem_u32(&Bs[st][0]);
#pragma unroll
        for (int kk = 0; kk < 64; kk += 16) {
            uint32_t af[2][4], bfr[4][4];
#pragma unroll
            for (int mt = 0; mt < 2; mt++) {
                int row = warp_m * 32 + mt * 16 + (lane & 15);
                int col = kk + (lane >> 4) * 8;
                ldm_x4(af[mt], abase + (row * SSTR + col) * 2);
            }
#pragma unroll
            for (int bt = 0; bt < 4; bt++) {
                int row = warp_n * 64 + bt * 16 + (lane & 15);
                int col = kk + (lane >> 4) * 8;
                ldm_x4(bfr[bt], bbase + (row * SSTR + col) * 2);
            }
#pragma unroll
            for (int mt = 0; mt < 2; mt++)
#pragma unroll
                for (int bt = 0; bt < 4; bt++) {
                    uint32_t blo[2] = { bfr[bt][0], bfr[bt][2] };
                    uint32_t bhi[2] = { bfr[bt][1], bfr[bt][3] };
                    mma16816(acc[mt][bt * 2 + 0], af[mt], blo);
                    mma16816(acc[mt][bt * 2 + 1], af[mt], bhi);
                }
        }
    }

    // epilogue: c fragment rows lane>>2 (+8), cols (lane&3)*2 (+1)
    int rbase = gm * 128 + warp_m * 32;
    int cbase = gn * 128 + warp_n * 64;
#pragma unroll
    for (int mt = 0; mt < 2; mt++) {
#pragma unroll
        for (int nt = 0; nt < 8; nt++) {
#pragma unroll
            for (int hf = 0; hf < 2; hf++) {
                int grow = rbase + mt * 16 + (lane >> 2) + hf * 8;
                int gcol = cbase + nt * 8 + (lane & 3) * 2;
                float v0 = acc[mt][nt][hf * 2 + 0];
                float v1 = acc[mt][nt][hf * 2 + 1];
                if (bias) { v0 += bias[gcol]; v1 += bias[gcol + 1]; }
                if (MODE == 2) {
                    const float* rr = res + (size_t)grow * N + gcol;
                    v0 += rr[0]; v1 += rr[1];
                }
                if (MODE == 1) {
                    v0 = fmaxf(v0, 0.f); v1 = fmaxf(v1, 0.f);
                    size_t o = (size_t)grow * (3 * (size_t)KoutS) + gcol;
                    split_store(outS, o,     KoutS, v0);
                    split_store(outS, o + 1, KoutS, v1);
                } else {
                    float* po = outF + (size_t)grow * N + gcol;
                    po[0] = v0; po[1] = v1;
                }
            }
        }
    }
}

// ================= weight packing =================
__device__ __forceinline__ void tsplit_body(const float* __restrict__ src,
                                            bf16* __restrict__ dst,
                                            int K, int N, int n0, int k0,
                                            int tx, int ty, float (*t)[33]) {
#pragma unroll
    for (int i = 0; i < 32; i += 8) t[ty + i][tx] = src[(size_t)(k0 + ty + i) * N + n0 + tx];
    __syncthreads();
#pragma unroll
    for (int i = 0; i < 32; i += 8) {
        float v = t[tx][ty + i];
        int n = n0 + ty + i, k = k0 + tx;
        bf16 h = __float2bfloat16(v);
        bf16 l = __float2bfloat16(v - __bfloat162float(h));
        size_t o = (size_t)n * (3 * (size_t)K) + k;
        dst[o] = h; dst[o + K] = h; dst[o + 2 * K] = l;
    }
}

// src [K,N] fp32 -> dst [N,3K] bf16 K-major: [hi | hi | lo]
__global__ void tsplit_kernel(const float* __restrict__ src, bf16* __restrict__ dst,
                              int K, int N) {
    __shared__ float t[32][33];
    tsplit_body(src, dst, K, N, blockIdx.x * 32, blockIdx.y * 32,
                threadIdx.x, threadIdx.y, t);
}

// all proj/f1/f2 packs in ONE launch
__global__ void tsplit_multi(const float* __restrict__ wproj,
                             const float* __restrict__ wf1,
                             const float* __restrict__ wf2) {
    __shared__ float t[32][33];
    int id = blockIdx.x;
    int blk = id / 14400, r = id % 14400;
    const float* src; bf16* dst; int K, N, tn, tk;
    if (r < 576) {
        src = wproj + (size_t)blk * 768 * 768;  dst = g_wprojB + (size_t)blk * 768 * 2304;
        K = 768; N = 768; tn = r % 24; tk = r / 24;
    } else if (r < 7488) {
        int q = r - 576;
        src = wf1 + (size_t)blk * 768 * 9216;   dst = g_wf1B + (size_t)blk * 9216 * 2304;
        K = 768; N = 9216; tn = q % 288; tk = q / 288;
    } else {
        int q = r - 7488;
        src = wf2 + (size_t)blk * 9216 * 768;   dst = g_wf2B + (size_t)blk * 768 * 27648;
        K = 9216; N = 768; tn = q % 24; tk = q / 24;
    }
    tsplit_body(src, dst, K, N, tn * 32, tk * 32, threadIdx.x, threadIdx.y, t);
}

// wq/wk/wv [blk][H][768][64] -> g_wqkvB [blk][N=2304][3K=2304]
__global__ void qkvpack_kernel(const float* __restrict__ wq, const float* __restrict__ wk,
                               const float* __restrict__ wv) {
    __shared__ float t[32][33];
    int z = blockIdx.z;
    int blk = z / 36, rem = z % 36, mat = rem / 12, h = rem % 12;
    const float* src = (mat == 0 ? wq : mat == 1 ? wk : wv) + (size_t)(blk * 12 + h) * 768 * 64;
    int d0 = blockIdx.x * 32, c0 = blockIdx.y * 32;
    int tx = threadIdx.x, ty = threadIdx.y;
#pragma unroll
    for (int i = 0; i < 32; i += 8) t[ty + i][tx] = src[(size_t)(c0 + ty + i) * 64 + d0 + tx];
    __syncthreads();
    bf16* dst = g_wqkvB + (size_t)blk * 2304 * 2304;
#pragma unroll
    for (int i = 0; i < 32; i += 8) {
        float v = t[tx][ty + i];
        int n = mat * 768 + h * 64 + d0 + ty + i;
        int c = c0 + tx;
        bf16 hh = __float2bfloat16(v);
        bf16 ll = __float2bfloat16(v - __bfloat162float(hh));
        size_t o = (size_t)n * 2304 + c;
        dst[o] = hh; dst[o + 768] = hh; dst[o + 1536] = ll;
    }
}

// ================= embed =================
__global__ void embed_kernel(const float* __restrict__ tok, const float* __restrict__ pos,
                             const int* __restrict__ src) {
    int idx = blockIdx.x * blockDim.x + threadIdx.x;
    if (idx >= Mrows * Cc) return;
    int r = idx / Cc, c = idx % Cc;
    g_x[idx] = tok[(size_t)src[r] * Cc + c] + pos[(size_t)(r % Tt) * Cc + c];
}

// ================= LayerNorm -> split bf16 =================
__global__ void ln_kernel(const float* __restrict__ x, const float* __restrict__ g,
                          const float* __restrict__ b) {
    int r = blockIdx.x, tid = threadIdx.x;
    const float* xr = x + (size_t)r * Cc;
    float vals[3];
    float s = 0.f, ss = 0.f;
#pragma unroll
    for (int i = 0; i < 3; i++) {
        float v = xr[tid + i * 256];
        vals[i] = v; s += v; ss += v * v;
    }
#pragma unroll
    for (int o = 16; o; o >>= 1) {
        s  += __shfl_xor_sync(0xffffffffu, s,  o);
        ss += __shfl_xor_sync(0xffffffffu, ss, o);
    }
    __shared__ float sh_s[8], sh_ss[8], smean, srstd;
    int w = tid >> 5, l = tid & 31;
    if (l == 0) { sh_s[w] = s; sh_ss[w] = ss; }
    __syncthreads();
    if (tid == 0) {
        float S = 0.f, SS = 0.f;
        for (int i = 0; i < 8; i++) { S += sh_s[i]; SS += sh_ss[i]; }
        float m = S / Cc;
        smean = m; srstd = rsqrtf(SS / Cc - m * m + 1e-5f);
    }
    __syncthreads();
    float m = smean, rstd = srstd;
#pragma unroll
    for (int i = 0; i < 3; i++) {
        int c = tid + i * 256;
        float y = (vals[i] - m) * rstd * g[c] + b[c];
        split_store(g_asp, (size_t)r * 2304 + c, 768, y);
    }
}

// ================= causal attention (fp32), split output =================
__global__ void __launch_bounds__(256)
attn_kernel(const float* __restrict__ QKV) {
    int bh = blockIdx.x;
    int b = bh / Hh, h = bh % Hh;
    int qt0 = blockIdx.y * 64;
    int tid = threadIdx.x;

    __shared__ float Qs[64][64];
    __shared__ float Ks[32][65];
    __shared__ float Vs[32][65];
    __shared__ float Ps[64][33];
    __shared__ float mrow[64], lrow[64], arow_s[64];

#pragma unroll
    for (int i = 0; i < 16; i++) {
        int e = tid + i * 256;
        int r = e >> 6, d = e & 63;
        Qs[r][d] = QKV[((size_t)(b * Tt + qt0 + r)) * QKVN + h * 64 + d];
    }
    if (tid < 64) { mrow[tid] = -1e30f; lrow[tid] = 0.f; }

    float o[16];
#pragma unroll
    for (int i = 0; i < 16; i++) o[i] = 0.f;

    int d_o = tid & 63, rg_o = tid >> 6;
    int s_s = tid & 31, rg_s = tid >> 5;

    int nkt = (qt0 + 64) / 32;
    for (int kt = 0; kt < nkt; kt++) {
        __syncthreads();
#pragma unroll
        for (int i = 0; i < 8; i++) {
            int e = tid + i * 256;
            int s = e >> 6, d = e & 63;
            size_t gi = ((size_t)(b * Tt + kt * 32 + s)) * QKVN + h * 64 + d;
            Ks[s][d] = QKV[gi + 768];
            Vs[s][d] = QKV[gi + 1536];
        }
        __syncthreads();
#pragma unroll
        for (int i = 0; i < 8; i++) {
            int r = rg_s * 8 + i;
            float a = 0.f;
#pragma unroll
            for (int k = 0; k < 64; k++) a += Qs[r][k] * Ks[s_s][k];
            int sg = kt * 32 + s_s, tg = qt0 + r;
            Ps[r][s_s] = (sg <= tg) ? a * ATT_SCALE : -1e30f;
        }
        __syncthreads();
        if (tid < 64) {
            int r = tid;
            float m_old = mrow[r], mx = m_old;
#pragma unroll
            for (int s = 0; s < 32; s++) mx = fmaxf(mx, Ps[r][s]);
            float alpha = expf(m_old - mx), sum = 0.f;
#pragma unroll
            for (int s = 0; s < 32; s++) { float p = expf(Ps[r][s] - mx); Ps[r][s] = p; sum += p; }
            mrow[r] = mx; lrow[r] = lrow[r] * alpha + sum; arow_s[r] = alpha;
        }
        __syncthreads();
#pragma unroll
        for (int i = 0; i < 16; i++) {
            int r = rg_o * 16 + i;
            float al = arow_s[r], a = 0.f;
#pragma unroll
            for (int s = 0; s < 32; s++) a += Ps[r][s] * Vs[s][d_o];
            o[i] = o[i] * al + a;
        }
    }
#pragma unroll
    for (int i = 0; i < 16; i++) {
        int r = rg_o * 16 + i;
        float v = o[i] / lrow[r];
        split_store(g_asp, ((size_t)(b * Tt + qt0 + r)) * 2304 + h * 64 + d_o, 768, v);
    }
}

// ================= loss (one-pass online softmax) =================
__global__ void loss_rows_kernel(const float* __restrict__ logits, const int* __restrict__ targets) {
    int r = blockIdx.x, tid = threadIdx.x;
    const float* row = logits + (size_t)r * Vv;
    float mx = -1e30f, s = 0.f;
    for (int c = tid; c < Vv; c += 256) {
        float v = row[c];
        if (v > mx) { s = s * expf(mx - v) + 1.f; mx = v; }
        else        { s += expf(v - mx); }
    }
#pragma unroll
    for (int o = 16; o; o >>= 1) {
        float mo = __shfl_xor_sync(0xffffffffu, mx, o);
        float so = __shfl_xor_sync(0xffffffffu, s,  o);
        float M = fmaxf(mx, mo);
        s = s * expf(mx - M) + so * expf(mo - M);
        mx = M;
    }
    __shared__ float shm[8], shs[8];
    int w = tid >> 5;
    if ((tid & 31) == 0) { shm[w] = mx; shs[w] = s; }
    __syncthreads();
    if (tid == 0) {
        float M = shm[0];
        for (int i = 1; i < 8; i++) M = fmaxf(M, shm[i]);
        float S = 0.f;
        for (int i = 0; i < 8; i++) S += shs[i] * expf(shm[i] - M);
        g_rowloss[r] = M + logf(S) - row[targets[r]];
    }
}

__global__ void loss_reduce_kernel(float* __restrict__ d_out, long long out_size) {
    int tid = threadIdx.x;
    __shared__ float sh[8];
    float s = 0.f;
    for (int i = tid; i < Mrows; i += 256) s += g_rowloss[i];
#pragma unroll
    for (int o = 16; o; o >>= 1) s += __shfl_xor_sync(0xffffffffu, s, o);
    if ((tid & 31) == 0) sh[tid >> 5] = s;
    __syncthreads();
    if (tid == 0) {
        float S = 0.f;
        for (int i = 0; i < 8; i++) S += sh[i];
        float loss = S / (float)Mrows;
        for (long long i = LOGITS_N; i < out_size; i++) d_out[i] = loss;
    }
}

// ================= host orchestration =================
extern "C" void kernel_launch(void* const* d_in, const int* in_sizes, int n_in,
                              void* d_out, int out_size) {
    const float* tok_emb = (const float*)d_in[0];
    const float* pos_emb = (const float*)d_in[1];
    const float* wq      = (const float*)d_in[2];
    const float* wk      = (const float*)d_in[3];
    const float* wv      = (const float*)d_in[4];
    const float* wproj   = (const float*)d_in[5];
    const float* bproj   = (const float*)d_in[6];
    const float* g1      = (const float*)d_in[7];
    const float* b1      = (const float*)d_in[8];
    const float* g2      = (const float*)d_in[9];
    const float* b2      = (const float*)d_in[10];
    const float* wf1     = (const float*)d_in[11];
    const float* bf1     = (const float*)d_in[12];
    const float* wf2     = (const float*)d_in[13];
    const float* bf2     = (const float*)d_in[14];
    const float* gf      = (const float*)d_in[15];
    const float* bfv     = (const float*)d_in[16];
    const float* wlm     = (const float*)d_in[17];
    const float* blm     = (const float*)d_in[18];
    const int*   sources = (const int*)d_in[19];
    const int*   targets = (const int*)d_in[20];
    float* out = (float*)d_out;

    float *px, *pqkv;
    bf16 *pasp, *pffsp, *pwqkv, *pwproj, *pwf1, *pwf2, *pwlm;
    cudaGetSymbolAddress((void**)&px,    g_x);
    cudaGetSymbolAddress((void**)&pqkv,  g_qkv);
    cudaGetSymbolAddress((void**)&pasp,  g_asp);
    cudaGetSymbolAddress((void**)&pffsp, g_ffsp);
    cudaGetSymbolAddress((void**)&pwqkv, g_wqkvB);
    cudaGetSymbolAddress((void**)&pwproj,g_wprojB);
    cudaGetSymbolAddress((void**)&pwf1,  g_wf1B);
    cudaGetSymbolAddress((void**)&pwf2,  g_wf2B);
    cudaGetSymbolAddress((void**)&pwlm,  g_wlmB);

    dim3 tb32(32, 8);
    // launch order: model kernels occupy slots ~5-7 so ncu -s 5 -c 1 lands on
    // QKV gemm or attention.
    embed_kernel<<<(Mrows * Cc + 255) / 256, 256>>>(tok_emb, pos_emb, sources);   // 1
    qkvpack_kernel<<<dim3(2, 24, 108), tb32>>>(wq, wk, wv);                       // 2
    tsplit_multi<<<43200, tb32>>>(wproj, wf1, wf2);                               // 3
    ln_kernel<<<Mrows, 256>>>(px, g1 + 0 * Cc, b1 + 0 * Cc);                      // 4

    for (int i = 0; i < NB; i++) {
        if (i > 0) ln_kernel<<<Mrows, 256>>>(px, g1 + i * Cc, b1 + i * Cc);
        hmma_gemm<0><<<dim3(32, 18), 256>>>(                                      // 5 on i=0
            pasp, pwqkv + (size_t)i*2304*2304, nullptr, nullptr, pqkv, nullptr, 2304, QKVN, 0);
        attn_kernel<<<dim3(NBATCH * Hh, Tt / 64), 256>>>(pqkv);                   // 6 on i=0
        hmma_gemm<2><<<dim3(32, 6), 256>>>(                                       // 7 on i=0
            pasp, pwproj + (size_t)i*768*2304, bproj + i * Cc, px, px, nullptr, 2304, Cc, 0);
        ln_kernel<<<Mrows, 256>>>(px, g2 + i * Cc, b2 + i * Cc);
        hmma_gemm<1><<<dim3(32, 72), 256>>>(
            pasp, pwf1 + (size_t)i*9216*2304, bf1 + i * FFf, nullptr, nullptr, pffsp, 2304, FFf, FFf);
        hmma_gemm<2><<<dim3(32, 6), 256>>>(
            pffsp, pwf2 + (size_t)i*768*27648, bf2 + i * Cc, px, px, nullptr, 27648, Cc, 0);
    }

    tsplit_kernel<<<dim3(1000, 24), tb32>>>(wlm, pwlm, 768, Vv);   // LM pack late
    ln_kernel<<<Mrows, 256>>>(px, gf, bfv);
    hmma_gemm<0><<<dim3(32, 250), 256>>>(
        pasp, pwlm, blm, nullptr, out, nullptr, 2304, Vv, 0);

    loss_rows_kernel<<<Mrows, 256>>>(out, targets);
    loss_reduce_kernel<<<1, 256>>>(out, (long long)out_size);
}

// round 16
// speedup vs baseline: 1.2020x; 1.0391x over previous
#include <cuda_runtime.h>
#include <cuda_bf16.h>
#include <math.h>
#include <stdint.h>

#define Vv    32000
#define Cc    768
#define Tt    1024
#define Hh    12
#define FFf   9216
#define NB    3
#define Mrows 4096
#define QKVN  2304
#define NBATCH 4
#define LOGITS_N 131072000LL
#define ATT_SCALE 0.036084391824351615f

typedef __nv_bfloat16 bf16;

// ---- scratch (device globals; no runtime allocation) ----
__device__ float g_x   [Mrows*Cc];
__device__ float g_qkv [Mrows*QKVN];
__device__ __align__(128) bf16 g_asp [(size_t)Mrows*2304];        // split activations [M, 3*768] = [hi|lo|hi]
__device__ __align__(128) bf16 g_ffsp[(size_t)Mrows*27648];       // split FF activations [M, 3*9216]
__device__ float g_rowloss[Mrows];
// split, transposed weights: [N, 3K] bf16, K-major, [hi | hi | lo]
__device__ __align__(128) bf16 g_wqkvB [(size_t)NB*2304*2304];
__device__ __align__(128) bf16 g_wprojB[(size_t)NB*768*2304];
__device__ __align__(128) bf16 g_wf1B  [(size_t)NB*9216*2304];
__device__ __align__(128) bf16 g_wf2B  [(size_t)NB*768*27648];
__device__ __align__(128) bf16 g_wlmB  [(size_t)Vv*2304];

// ================= PTX helpers (arch-portable, sm_80+) =================
__device__ __forceinline__ uint32_t smem_u32(const void* p) {
    uint32_t a;
    asm("{ .reg .u64 t; cvta.to.shared.u64 t, %1; cvt.u32.u64 %0, t; }" : "=r"(a) : "l"(p));
    return a;
}
#define CP16(dst, src)  asm volatile("cp.async.cg.shared.global [%0], [%1], 16;" :: "r"(dst), "l"(src))
#define CP_COMMIT()     asm volatile("cp.async.commit_group;" ::: "memory")
#define CP_WAITG(n)     asm volatile("cp.async.wait_group %0;" :: "n"(n) : "memory")

__device__ __forceinline__ void ldm_x4(uint32_t* r, uint32_t addr) {
    asm volatile("ldmatrix.sync.aligned.m8n8.x4.shared.b16 {%0,%1,%2,%3}, [%4];"
        : "=r"(r[0]), "=r"(r[1]), "=r"(r[2]), "=r"(r[3]) : "r"(addr));
}
__device__ __forceinline__ void mma16816(float* c, const uint32_t* a, const uint32_t* b) {
    asm volatile("mma.sync.aligned.m16n8k16.row.col.f32.bf16.bf16.f32 "
        "{%0,%1,%2,%3}, {%4,%5,%6,%7}, {%8,%9}, {%0,%1,%2,%3};"
        : "+f"(c[0]), "+f"(c[1]), "+f"(c[2]), "+f"(c[3])
        : "r"(a[0]), "r"(a[1]), "r"(a[2]), "r"(a[3]), "r"(b[0]), "r"(b[1]));
}

__device__ __forceinline__ void split_store(bf16* p, size_t o, size_t K, float v) {
    bf16 h = __float2bfloat16(v);
    bf16 l = __float2bfloat16(v - __bfloat162float(h));
    p[o] = h; p[o + K] = l; p[o + 2*K] = h;   // A layout: [hi | lo | hi]
}

#define SSTR 72   // smem row stride (144B): ldmatrix rows start at banks {0,4,...,28} -> conflict-free

// ================= HMMA GEMM, 128x128 tile (QKV / FF1 / LM head) =================
// BK=64 double-buffered, 256 threads, 8 warps (4m x 2n, warp tile 32x64), 2 CTAs/SM.
// MODE 0: outF = acc (+bias)   MODE 1: relu(acc+bias) -> split bf16 outS
// MODE 2: outF = acc + bias + res
template<int MODE>
__global__ void __launch_bounds__(256, 2)
hmma_gemm(const bf16* __restrict__ A, const bf16* __restrict__ Bw,
          const float* __restrict__ bias, const float* __restrict__ res,
          float* __restrict__ outF, bf16* __restrict__ outS,
          int K3, int N, int KoutS)
{
    __shared__ __align__(16) bf16 As[2][128 * SSTR];
    __shared__ __align__(16) bf16 Bs[2][128 * SSTR];

    int tid = threadIdx.x, lane = tid & 31, wid = tid >> 5;
    int warp_m = wid & 3, warp_n = wid >> 2;
    int gm = blockIdx.x, gn = blockIdx.y;

    const bf16* Aptr = A  + (size_t)(gm * 128) * K3;
    const bf16* Bptr = Bw + (size_t)(gn * 128) * K3;

    float acc[2][8][4];
#pragma unroll
    for (int i = 0; i < 2; i++)
#pragma unroll
        for (int j = 0; j < 8; j++)
#pragma unroll
            for (int q = 0; q < 4; q++) acc[i][j][q] = 0.f;

    auto load_tiles = [&](int stage, int k0) {
        uint32_t sa = smem_u32(&As[stage][0]);
        uint32_t sb = smem_u32(&Bs[stage][0]);
#pragma unroll
        for (int it2 = 0; it2 < 4; it2++) {
            int e = tid + it2 * 256;
            int row = e >> 3, sub = (e & 7) * 8;
            CP16(sa + (row * SSTR + sub) * 2, Aptr + (size_t)row * K3 + k0 + sub);
        }
#pragma unroll
        for (int it2 = 0; it2 < 4; it2++) {
            int e = tid + it2 * 256;
            int row = e >> 3, sub = (e & 7) * 8;
            CP16(sb + (row * SSTR + sub) * 2, Bptr + (size_t)row * K3 + k0 + sub);
        }
        CP_COMMIT();
    };

    int NK = K3 / 64;
    load_tiles(0, 0);

    for (int it = 0; it < NK; it++) {
        CP_WAITG(0);
        __syncthreads();

        if (it + 1 < NK) load_tiles((it + 1) & 1, (it + 1) * 64);

        int st = it & 1;
        uint32_t abase = smem_u32(&As[st][0]);
        uint32_t bbase = smem_u32(&Bs[st][0]);
#pragma unroll
        for (int kk = 0; kk < 64; kk += 16) {
            uint32_t af[2][4], bfr[4][4];
#pragma unroll
            for (int mt = 0; mt < 2; mt++) {
                int row = warp_m * 32 + mt * 16 + (lane & 15);
                int col = kk + (lane >> 4) * 8;
                ldm_x4(af[mt], abase + (row * SSTR + col) * 2);
            }
#pragma unroll
            for (int bt = 0; bt < 4; bt++) {
                int row = warp_n * 64 + bt * 16 + (lane & 15);
                int col = kk + (lane >> 4) * 8;
                ldm_x4(bfr[bt], bbase + (row * SSTR + col) * 2);
            }
#pragma unroll
            for (int mt = 0; mt < 2; mt++)
#pragma unroll
                for (int bt = 0; bt < 4; bt++) {
                    uint32_t blo[2] = { bfr[bt][0], bfr[bt][2] };
                    uint32_t bhi[2] = { bfr[bt][1], bfr[bt][3] };
                    mma16816(acc[mt][bt * 2 + 0], af[mt], blo);
                    mma16816(acc[mt][bt * 2 + 1], af[mt], bhi);
                }
        }
    }

    int rbase = gm * 128 + warp_m * 32;
    int cbase = gn * 128 + warp_n * 64;
#pragma unroll
    for (int mt = 0; mt < 2; mt++) {
#pragma unroll
        for (int nt = 0; nt < 8; nt++) {
#pragma unroll
            for (int hf = 0; hf < 2; hf++) {
                int grow = rbase + mt * 16 + (lane >> 2) + hf * 8;
                int gcol = cbase + nt * 8 + (lane & 3) * 2;
                float v0 = acc[mt][nt][hf * 2 + 0];
                float v1 = acc[mt][nt][hf * 2 + 1];
                if (bias) { v0 += bias[gcol]; v1 += bias[gcol + 1]; }
                if (MODE == 2) {
                    const float* rr = res + (size_t)grow * N + gcol;
                    v0 += rr[0]; v1 += rr[1];
                }
                if (MODE == 1) {
                    v0 = fmaxf(v0, 0.f); v1 = fmaxf(v1, 0.f);
                    size_t o = (size_t)grow * (3 * (size_t)KoutS) + gcol;
                    split_store(outS, o,     KoutS, v0);
                    split_store(outS, o + 1, KoutS, v1);
                } else {
                    float* po = outF + (size_t)grow * N + gcol;
                    po[0] = v0; po[1] = v1;
                }
            }
        }
    }
}

// ================= HMMA GEMM, 64x128 tile (proj / FF2: fine-grained balance) =================
// BK=64 double-buffered, 128 threads, 4 warps (2m x 2n, warp tile 32x64), 4 CTAs/SM.
// MODE 2 only: outF = acc + bias + res
__global__ void __launch_bounds__(128, 4)
hmma_gemm64(const bf16* __restrict__ A, const bf16* __restrict__ Bw,
            const float* __restrict__ bias, const float* __restrict__ res,
            float* __restrict__ outF, int K3, int N)
{
    __shared__ __align__(16) bf16 As[2][64 * SSTR];
    __shared__ __align__(16) bf16 Bs[2][128 * SSTR];

    int tid = threadIdx.x, lane = tid & 31, wid = tid >> 5;
    int warp_m = wid & 1, warp_n = wid >> 1;     // 2 x 2 warps, warp tile 32x64
    int gm = blockIdx.x, gn = blockIdx.y;

    const bf16* Aptr = A  + (size_t)(gm * 64) * K3;
    const bf16* Bptr = Bw + (size_t)(gn * 128) * K3;

    float acc[2][8][4];
#pragma unroll
    for (int i = 0; i < 2; i++)
#pragma unroll
        for (int j = 0; j < 8; j++)
#pragma unroll
            for (int q = 0; q < 4; q++) acc[i][j][q] = 0.f;

    // A stage: 64x64 = 512 segs (4/thread); B stage: 128x64 = 1024 segs (8/thread)
    auto load_tiles = [&](int stage, int k0) {
        uint32_t sa = smem_u32(&As[stage][0]);
        uint32_t sb = smem_u32(&Bs[stage][0]);
#pragma unroll
        for (int it2 = 0; it2 < 4; it2++) {
            int e = tid + it2 * 128;
            int row = e >> 3, sub = (e & 7) * 8;
            CP16(sa + (row * SSTR + sub) * 2, Aptr + (size_t)row * K3 + k0 + sub);
        }
#pragma unroll
        for (int it2 = 0; it2 < 8; it2++) {
            int e = tid + it2 * 128;
            int row = e >> 3, sub = (e & 7) * 8;
            CP16(sb + (row * SSTR + sub) * 2, Bptr + (size_t)row * K3 + k0 + sub);
        }
        CP_COMMIT();
    };

    int NK = K3 / 64;
    load_tiles(0, 0);

    for (int it = 0; it < NK; it++) {
        CP_WAITG(0);
        __syncthreads();

        if (it + 1 < NK) load_tiles((it + 1) & 1, (it + 1) * 64);

        int st = it & 1;
        uint32_t abase = smem_u32(&As[st][0]);
        uint32_t bbase = smem_u32(&Bs[st][0]);
#pragma unroll
        for (int kk = 0; kk < 64; kk += 16) {
            uint32_t af[2][4], bfr[4][4];
#pragma unroll
            for (int mt = 0; mt < 2; mt++) {
                int row = warp_m * 32 + mt * 16 + (lane & 15);
                int col = kk + (lane >> 4) * 8;
                ldm_x4(af[mt], abase + (row * SSTR + col) * 2);
            }
#pragma unroll
            for (int bt = 0; bt < 4; bt++) {
                int row = warp_n * 64 + bt * 16 + (lane & 15);
                int col = kk + (lane >> 4) * 8;
                ldm_x4(bfr[bt], bbase + (row * SSTR + col) * 2);
            }
#pragma unroll
            for (int mt = 0; mt < 2; mt++)
#pragma unroll
                for (int bt = 0; bt < 4; bt++) {
                    uint32_t blo[2] = { bfr[bt][0], bfr[bt][2] };
                    uint32_t bhi[2] = { bfr[bt][1], bfr[bt][3] };
                    mma16816(acc[mt][bt * 2 + 0], af[mt], blo);
                    mma16816(acc[mt][bt * 2 + 1], af[mt], bhi);
                }
        }
    }

    int rbase = gm * 64 + warp_m * 32;
    int cbase = gn * 128 + warp_n * 64;
#pragma unroll
    for (int mt = 0; mt < 2; mt++) {
#pragma unroll
        for (int nt = 0; nt < 8; nt++) {
#pragma unroll
            for (int hf = 0; hf < 2; hf++) {
                int grow = rbase + mt * 16 + (lane >> 2) + hf * 8;
                int gcol = cbase + nt * 8 + (lane & 3) * 2;
                float v0 = acc[mt][nt][hf * 2 + 0] + bias[gcol];
                float v1 = acc[mt][nt][hf * 2 + 1] + bias[gcol + 1];
                const float* rr = res + (size_t)grow * N + gcol;
                v0 += rr[0]; v1 += rr[1];
                float* po = outF + (size_t)grow * N + gcol;
                po[0] = v0; po[1] = v1;
            }
        }
    }
}

// ================= weight packing =================
__device__ __forceinline__ void tsplit_body(const float* __restrict__ src,
                                            bf16* __restrict__ dst,
                                            int K, int N, int n0, int k0,
                                            int tx, int ty, float (*t)[33]) {
#pragma unroll
    for (int i = 0; i < 32; i += 8) t[ty + i][tx] = src[(size_t)(k0 + ty + i) * N + n0 + tx];
    __syncthreads();
#pragma unroll
    for (int i = 0; i < 32; i += 8) {
        float v = t[tx][ty + i];
        int n = n0 + ty + i, k = k0 + tx;
        bf16 h = __float2bfloat16(v);
        bf16 l = __float2bfloat16(v - __bfloat162float(h));
        size_t o = (size_t)n * (3 * (size_t)K) + k;
        dst[o] = h; dst[o + K] = h; dst[o + 2 * K] = l;
    }
}

// src [K,N] fp32 -> dst [N,3K] bf16 K-major: [hi | hi | lo]
__global__ void tsplit_kernel(const float* __restrict__ src, bf16* __restrict__ dst,
                              int K, int N) {
    __shared__ float t[32][33];
    tsplit_body(src, dst, K, N, blockIdx.x * 32, blockIdx.y * 32,
                threadIdx.x, threadIdx.y, t);
}

// all proj/f1/f2 packs in ONE launch
__global__ void tsplit_multi(const float* __restrict__ wproj,
                             const float* __restrict__ wf1,
                             const float* __restrict__ wf2) {
    __shared__ float t[32][33];
    int id = blockIdx.x;
    int blk = id / 14400, r = id % 14400;
    const float* src; bf16* dst; int K, N, tn, tk;
    if (r < 576) {
        src = wproj + (size_t)blk * 768 * 768;  dst = g_wprojB + (size_t)blk * 768 * 2304;
        K = 768; N = 768; tn = r % 24; tk = r / 24;
    } else if (r < 7488) {
        int q = r - 576;
        src = wf1 + (size_t)blk * 768 * 9216;   dst = g_wf1B + (size_t)blk * 9216 * 2304;
        K = 768; N = 9216; tn = q % 288; tk = q / 288;
    } else {
        int q = r - 7488;
        src = wf2 + (size_t)blk * 9216 * 768;   dst = g_wf2B + (size_t)blk * 768 * 27648;
        K = 9216; N = 768; tn = q % 24; tk = q / 24;
    }
    tsplit_body(src, dst, K, N, tn * 32, tk * 32, threadIdx.x, threadIdx.y, t);
}

// wq/wk/wv [blk][H][768][64] -> g_wqkvB [blk][N=2304][3K=2304]
__global__ void qkvpack_kernel(const float* __restrict__ wq, const float* __restrict__ wk,
                               const float* __restrict__ wv) {
    __shared__ float t[32][33];
    int z = blockIdx.z;
    int blk = z / 36, rem = z % 36, mat = rem / 12, h = rem % 12;
    const float* src = (mat == 0 ? wq : mat == 1 ? wk : wv) + (size_t)(blk * 12 + h) * 768 * 64;
    int d0 = blockIdx.x * 32, c0 = blockIdx.y * 32;
    int tx = threadIdx.x, ty = threadIdx.y;
#pragma unroll
    for (int i = 0; i < 32; i += 8) t[ty + i][tx] = src[(size_t)(c0 + ty + i) * 64 + d0 + tx];
    __syncthreads();
    bf16* dst = g_wqkvB + (size_t)blk * 2304 * 2304;
#pragma unroll
    for (int i = 0; i < 32; i += 8) {
        float v = t[tx][ty + i];
        int n = mat * 768 + h * 64 + d0 + ty + i;
        int c = c0 + tx;
        bf16 hh = __float2bfloat16(v);
        bf16 ll = __float2bfloat16(v - __bfloat162float(hh));
        size_t o = (size_t)n * 2304 + c;
        dst[o] = hh; dst[o + 768] = hh; dst[o + 1536] = ll;
    }
}

// ================= embed =================
__global__ void embed_kernel(const float* __restrict__ tok, const float* __restrict__ pos,
                             const int* __restrict__ src) {
    int idx = blockIdx.x * blockDim.x + threadIdx.x;
    if (idx >= Mrows * Cc) return;
    int r = idx / Cc, c = idx % Cc;
    g_x[idx] = tok[(size_t)src[r] * Cc + c] + pos[(size_t)(r % Tt) * Cc + c];
}

// ================= LayerNorm -> split bf16 =================
__global__ void ln_kernel(const float* __restrict__ x, const float* __restrict__ g,
                          const float* __restrict__ b) {
    int r = blockIdx.x, tid = threadIdx.x;
    const float* xr = x + (size_t)r * Cc;
    float vals[3];
    float s = 0.f, ss = 0.f;
#pragma unroll
    for (int i = 0; i < 3; i++) {
        float v = xr[tid + i * 256];
        vals[i] = v; s += v; ss += v * v;
    }
#pragma unroll
    for (int o = 16; o; o >>= 1) {
        s  += __shfl_xor_sync(0xffffffffu, s,  o);
        ss += __shfl_xor_sync(0xffffffffu, ss, o);
    }
    __shared__ float sh_s[8], sh_ss[8], smean, srstd;
    int w = tid >> 5, l = tid & 31;
    if (l == 0) { sh_s[w] = s; sh_ss[w] = ss; }
    __syncthreads();
    if (tid == 0) {
        float S = 0.f, SS = 0.f;
        for (int i = 0; i < 8; i++) { S += sh_s[i]; SS += sh_ss[i]; }
        float m = S / Cc;
        smean = m; srstd = rsqrtf(SS / Cc - m * m + 1e-5f);
    }
    __syncthreads();
    float m = smean, rstd = srstd;
#pragma unroll
    for (int i = 0; i < 3; i++) {
        int c = tid + i * 256;
        float y = (vals[i] - m) * rstd * g[c] + b[c];
        split_store(g_asp, (size_t)r * 2304 + c, 768, y);
    }
}

// ================= causal attention (fp32), split output =================
__global__ void __launch_bounds__(256)
attn_kernel(const float* __restrict__ QKV) {
    int bh = blockIdx.x;
    int b = bh / Hh, h = bh % Hh;
    int qt0 = blockIdx.y * 64;
    int tid = threadIdx.x;

    __shared__ float Qs[64][64];
    __shared__ float Ks[32][65];
    __shared__ float Vs[32][65];
    __shared__ float Ps[64][33];
    __shared__ float mrow[64], lrow[64], arow_s[64];

#pragma unroll
    for (int i = 0; i < 16; i++) {
        int e = tid + i * 256;
        int r = e >> 6, d = e & 63;
        Qs[r][d] = QKV[((size_t)(b * Tt + qt0 + r)) * QKVN + h * 64 + d];
    }
    if (tid < 64) { mrow[tid] = -1e30f; lrow[tid] = 0.f; }

    float o[16];
#pragma unroll
    for (int i = 0; i < 16; i++) o[i] = 0.f;

    int d_o = tid & 63, rg_o = tid >> 6;
    int s_s = tid & 31, rg_s = tid >> 5;

    int nkt = (qt0 + 64) / 32;
    for (int kt = 0; kt < nkt; kt++) {
        __syncthreads();
#pragma unroll
        for (int i = 0; i < 8; i++) {
            int e = tid + i * 256;
            int s = e >> 6, d = e & 63;
            size_t gi = ((size_t)(b * Tt + kt * 32 + s)) * QKVN + h * 64 + d;
            Ks[s][d] = QKV[gi + 768];
            Vs[s][d] = QKV[gi + 1536];
        }
        __syncthreads();
#pragma unroll
        for (int i = 0; i < 8; i++) {
            int r = rg_s * 8 + i;
            float a = 0.f;
#pragma unroll
            for (int k = 0; k < 64; k++) a += Qs[r][k] * Ks[s_s][k];
            int sg = kt * 32 + s_s, tg = qt0 + r;
            Ps[r][s_s] = (sg <= tg) ? a * ATT_SCALE : -1e30f;
        }
        __syncthreads();
        if (tid < 64) {
            int r = tid;
            float m_old = mrow[r], mx = m_old;
#pragma unroll
            for (int s = 0; s < 32; s++) mx = fmaxf(mx, Ps[r][s]);
            float alpha = expf(m_old - mx), sum = 0.f;
#pragma unroll
            for (int s = 0; s < 32; s++) { float p = expf(Ps[r][s] - mx); Ps[r][s] = p; sum += p; }
            mrow[r] = mx; lrow[r] = lrow[r] * alpha + sum; arow_s[r] = alpha;
        }
        __syncthreads();
#pragma unroll
        for (int i = 0; i < 16; i++) {
            int r = rg_o * 16 + i;
            float al = arow_s[r], a = 0.f;
#pragma unroll
            for (int s = 0; s < 32; s++) a += Ps[r][s] * Vs[s][d_o];
            o[i] = o[i] * al + a;
        }
    }
#pragma unroll
    for (int i = 0; i < 16; i++) {
        int r = rg_o * 16 + i;
        float v = o[i] / lrow[r];
        split_store(g_asp, ((size_t)(b * Tt + qt0 + r)) * 2304 + h * 64 + d_o, 768, v);
    }
}

// ================= loss (one-pass online softmax) =================
__global__ void loss_rows_kernel(const float* __restrict__ logits, const int* __restrict__ targets) {
    int r = blockIdx.x, tid = threadIdx.x;
    const float* row = logits + (size_t)r * Vv;
    float mx = -1e30f, s = 0.f;
    for (int c = tid; c < Vv; c += 256) {
        float v = row[c];
        if (v > mx) { s = s * expf(mx - v) + 1.f; mx = v; }
        else        { s += expf(v - mx); }
    }
#pragma unroll
    for (int o = 16; o; o >>= 1) {
        float mo = __shfl_xor_sync(0xffffffffu, mx, o);
        float so = __shfl_xor_sync(0xffffffffu, s,  o);
        float M = fmaxf(mx, mo);
        s = s * expf(mx - M) + so * expf(mo - M);
        mx = M;
    }
    __shared__ float shm[8], shs[8];
    int w = tid >> 5;
    if ((tid & 31) == 0) { shm[w] = mx; shs[w] = s; }
    __syncthreads();
    if (tid == 0) {
        float M = shm[0];
        for (int i = 1; i < 8; i++) M = fmaxf(M, shm[i]);
        float S = 0.f;
        for (int i = 0; i < 8; i++) S += shs[i] * expf(shm[i] - M);
        g_rowloss[r] = M + logf(S) - row[targets[r]];
    }
}

__global__ void loss_reduce_kernel(float* __restrict__ d_out, long long out_size) {
    int tid = threadIdx.x;
    __shared__ float sh[8];
    float s = 0.f;
    for (int i = tid; i < Mrows; i += 256) s += g_rowloss[i];
#pragma unroll
    for (int o = 16; o; o >>= 1) s += __shfl_xor_sync(0xffffffffu, s, o);
    if ((tid & 31) == 0) sh[tid >> 5] = s;
    __syncthreads();
    if (tid == 0) {
        float S = 0.f;
        for (int i = 0; i < 8; i++) S += sh[i];
        float loss = S / (float)Mrows;
        for (long long i = LOGITS_N; i < out_size; i++) d_out[i] = loss;
    }
}

// ================= host orchestration =================
extern "C" void kernel_launch(void* const* d_in, const int* in_sizes, int n_in,
                              void* d_out, int out_size) {
    const float* tok_emb = (const float*)d_in[0];
    const float* pos_emb = (const float*)d_in[1];
    const float* wq      = (const float*)d_in[2];
    const float* wk      = (const float*)d_in[3];
    const float* wv      = (const float*)d_in[4];
    const float* wproj   = (const float*)d_in[5];
    const float* bproj   = (const float*)d_in[6];
    const float* g1      = (const float*)d_in[7];
    const float* b1      = (const float*)d_in[8];
    const float* g2      = (const float*)d_in[9];
    const float* b2      = (const float*)d_in[10];
    const float* wf1     = (const float*)d_in[11];
    const float* bf1     = (const float*)d_in[12];
    const float* wf2     = (const float*)d_in[13];
    const float* bf2     = (const float*)d_in[14];
    const float* gf      = (const float*)d_in[15];
    const float* bfv     = (const float*)d_in[16];
    const float* wlm     = (const float*)d_in[17];
    const float* blm     = (const float*)d_in[18];
    const int*   sources = (const int*)d_in[19];
    const int*   targets = (const int*)d_in[20];
    float* out = (float*)d_out;

    float *px, *pqkv;
    bf16 *pasp, *pffsp, *pwqkv, *pwproj, *pwf1, *pwf2, *pwlm;
    cudaGetSymbolAddress((void**)&px,    g_x);
    cudaGetSymbolAddress((void**)&pqkv,  g_qkv);
    cudaGetSymbolAddress((void**)&pasp,  g_asp);
    cudaGetSymbolAddress((void**)&pffsp, g_ffsp);
    cudaGetSymbolAddress((void**)&pwqkv, g_wqkvB);
    cudaGetSymbolAddress((void**)&pwproj,g_wprojB);
    cudaGetSymbolAddress((void**)&pwf1,  g_wf1B);
    cudaGetSymbolAddress((void**)&pwf2,  g_wf2B);
    cudaGetSymbolAddress((void**)&pwlm,  g_wlmB);

    dim3 tb32(32, 8);
    embed_kernel<<<(Mrows * Cc + 255) / 256, 256>>>(tok_emb, pos_emb, sources);   // 1
    qkvpack_kernel<<<dim3(2, 24, 108), tb32>>>(wq, wk, wv);                       // 2
    tsplit_multi<<<43200, tb32>>>(wproj, wf1, wf2);                               // 3
    ln_kernel<<<Mrows, 256>>>(px, g1 + 0 * Cc, b1 + 0 * Cc);                      // 4

    for (int i = 0; i < NB; i++) {
        if (i > 0) ln_kernel<<<Mrows, 256>>>(px, g1 + i * Cc, b1 + i * Cc);
        hmma_gemm<0><<<dim3(32, 18), 256>>>(                                      // 5 on i=0
            pasp, pwqkv + (size_t)i*2304*2304, nullptr, nullptr, pqkv, nullptr, 2304, QKVN, 0);
        attn_kernel<<<dim3(NBATCH * Hh, Tt / 64), 256>>>(pqkv);                   // 6 on i=0
        hmma_gemm64<<<dim3(64, 6), 128>>>(                                        // 7 on i=0
            pasp, pwproj + (size_t)i*768*2304, bproj + i * Cc, px, px, 2304, Cc);
        ln_kernel<<<Mrows, 256>>>(px, g2 + i * Cc, b2 + i * Cc);
        hmma_gemm<1><<<dim3(32, 72), 256>>>(
            pasp, pwf1 + (size_t)i*9216*2304, bf1 + i * FFf, nullptr, nullptr, pffsp, 2304, FFf, FFf);
        hmma_gemm64<<<dim3(64, 6), 128>>>(
            pffsp, pwf2 + (size_t)i*768*27648, bf2 + i * Cc, px, px, 27648, Cc);
    }

    tsplit_kernel<<<dim3(1000, 24), tb32>>>(wlm, pwlm, 768, Vv);   // LM pack late
    ln_kernel<<<Mrows, 256>>>(px, gf, bfv);
    hmma_gemm<0><<<dim3(32, 250), 256>>>(
        pasp, pwlm, blm, nullptr, out, nullptr, 2304, Vv, 0);

    loss_rows_kernel<<<Mrows, 256>>>(out, targets);
    loss_reduce_kernel<<<1, 256>>>(out, (long long)out_size);
}